// round 1
// baseline (speedup 1.0000x reference)
#include <cuda_runtime.h>

#define D 256
#define BT 2048   // B*T = 2*1024

// Scratch for Q, K, V projections (static device globals — no allocation).
__device__ float g_Q[BT * D];
__device__ float g_K[BT * D];
__device__ float g_V[BT * D];

// ---------------------------------------------------------------------------
// Kernel 1: QKV projection GEMM.
//   C[t][i] = sum_d X[t][d] * W[i][d] + b[i]     (W row-major [D,D], x @ W^T)
// Tiling: BM=64, BN=64, BK=16, 256 threads, 4x4 register tile per thread.
// blockIdx.z in {0,1,2} selects (Wq,bq,g_Q) / (Wk,bk,g_K) / (Wv,bv,g_V).
// ---------------------------------------------------------------------------
__global__ __launch_bounds__(256) void qkv_gemm(
    const float* __restrict__ X,
    const float* __restrict__ Wq, const float* __restrict__ bq,
    const float* __restrict__ Wk, const float* __restrict__ bk,
    const float* __restrict__ Wv, const float* __restrict__ bv)
{
    const int which = blockIdx.z;
    const float* __restrict__ W = (which == 0) ? Wq : (which == 1) ? Wk : Wv;
    const float* __restrict__ b = (which == 0) ? bq : (which == 1) ? bk : bv;
    float* __restrict__ C = (which == 0) ? g_Q : (which == 1) ? g_K : g_V;

    __shared__ __align__(16) float As[16][64];  // [k][m]  (transposed on store)
    __shared__ __align__(16) float Bs[16][64];  // [k][n]

    const int tid  = threadIdx.x;
    const int row0 = blockIdx.x * 64;   // token block
    const int col0 = blockIdx.y * 64;   // output-feature block

    const int tx = tid % 16;            // thread col (N)
    const int ty = tid / 16;            // thread row (M)

    // Loader mapping: one float4 of A and one of B per thread per BK step.
    const int lr = tid / 4;             // 0..63 : row within tile
    const int lc = (tid % 4) * 4;       // 0,4,8,12 : k offset within BK

    float acc[4][4] = {};

    const float* aptr = &X[(row0 + lr) * D + lc];
    const float* bptr = &W[(col0 + lr) * D + lc];

    for (int kb = 0; kb < D; kb += 16) {
        float4 a = *(const float4*)(aptr + kb);
        float4 w = *(const float4*)(bptr + kb);
        As[lc + 0][lr] = a.x; As[lc + 1][lr] = a.y;
        As[lc + 2][lr] = a.z; As[lc + 3][lr] = a.w;
        Bs[lc + 0][lr] = w.x; Bs[lc + 1][lr] = w.y;
        Bs[lc + 2][lr] = w.z; Bs[lc + 3][lr] = w.w;
        __syncthreads();

        #pragma unroll
        for (int k = 0; k < 16; k++) {
            float4 av = *(const float4*)&As[k][ty * 4];
            float4 bv4 = *(const float4*)&Bs[k][tx * 4];
            float am[4] = {av.x, av.y, av.z, av.w};
            float bn[4] = {bv4.x, bv4.y, bv4.z, bv4.w};
            #pragma unroll
            for (int m = 0; m < 4; m++)
                #pragma unroll
                for (int n = 0; n < 4; n++)
                    acc[m][n] += am[m] * bn[n];
        }
        __syncthreads();
    }

    #pragma unroll
    for (int m = 0; m < 4; m++) {
        const int r = row0 + ty * 4 + m;
        #pragma unroll
        for (int n = 0; n < 4; n++) {
            const int c = col0 + tx * 4 + n;
            C[r * D + c] = acc[m][n] + b[c];
        }
    }
}

// ---------------------------------------------------------------------------
// Kernel 2: per-token outer-product softmax + weighted V sum.
// One CTA per token, thread i owns output feature i:
//   out_i = ( sum_j exp2(q_i * kc_j) * v_j ) / ( sum_j exp2(q_i * kc_j) )
// where kc_j = K_j * scale * log2(e) is folded once at load.
// MUFU(EX2)-bound by design: per 4 j's -> 2 LDS.128, 4 FMUL, 4 EX2, 4 FFMA, 4 FADD.
// ---------------------------------------------------------------------------
__device__ __forceinline__ float ex2(float x) {
    float y;
    asm("ex2.approx.f32 %0, %1;" : "=f"(y) : "f"(x));
    return y;
}

__global__ __launch_bounds__(256) void attn_kernel(float* __restrict__ out)
{
    const int t = blockIdx.x;
    const int i = threadIdx.x;

    __shared__ __align__(16) float sK[D];
    __shared__ __align__(16) float sV[D];

    // scale * log2(e) ; scale = 1/sqrt(256) = 1/16 exactly
    const float c = 1.4426950408889634f * (1.0f / 16.0f);

    const int base = t * D;
    sK[i] = g_K[base + i] * c;
    sV[i] = g_V[base + i];
    const float q = g_Q[base + i];
    __syncthreads();

    float num = 0.f, den = 0.f;
    const float4* k4p = (const float4*)sK;
    const float4* v4p = (const float4*)sV;

    #pragma unroll 8
    for (int j4 = 0; j4 < D / 4; j4++) {
        float4 k4 = k4p[j4];   // broadcast LDS.128 (all threads same addr)
        float4 v4 = v4p[j4];
        float e0 = ex2(q * k4.x);
        float e1 = ex2(q * k4.y);
        float e2 = ex2(q * k4.z);
        float e3 = ex2(q * k4.w);
        num += e0 * v4.x;
        num += e1 * v4.y;
        num += e2 * v4.z;
        num += e3 * v4.w;
        den += e0;
        den += e1;
        den += e2;
        den += e3;
    }

    out[base + i] = num / den;
}

// ---------------------------------------------------------------------------
// Launch. Inputs (metadata order): x, Wq, bq, Wk, bk, Wv, bv. Output fp32.
// ---------------------------------------------------------------------------
extern "C" void kernel_launch(void* const* d_in, const int* in_sizes, int n_in,
                              void* d_out, int out_size)
{
    const float* x  = (const float*)d_in[0];
    const float* Wq = (const float*)d_in[1];
    const float* bq = (const float*)d_in[2];
    const float* Wk = (const float*)d_in[3];
    const float* bk = (const float*)d_in[4];
    const float* Wv = (const float*)d_in[5];
    const float* bv = (const float*)d_in[6];
    float* out = (float*)d_out;

    dim3 ggrid(BT / 64, D / 64, 3);   // 32 x 4 x 3 = 384 CTAs
    qkv_gemm<<<ggrid, 256>>>(x, Wq, bq, Wk, bk, Wv, bv);
    attn_kernel<<<BT, 256>>>(out);
}